// round 9
// baseline (speedup 1.0000x reference)
#include <cuda_runtime.h>
#include <cuda_bf16.h>

#define BATCH 16384
#define DIM   1024
#define DIM4  (DIM / 4)       // 256 float4 per row
#define NL    4

__device__ float g_D[NL];     // D_l = dot(c_l, W_l), c_l = sum_{j<l} b_j
__device__ float g_Csum[DIM]; // b0+b1+b2+b3

// ---------------------------------------------------------------------------
// Precompute: 1 CTA, 1024 threads, reads 32 KB.
// ---------------------------------------------------------------------------
__global__ __launch_bounds__(DIM) void crossnet_precompute(
    const float* __restrict__ W, const float* __restrict__ b)
{
    int d = threadIdx.x;
    float b0 = b[d];
    float b1 = b[DIM + d];
    float b2 = b[2 * DIM + d];
    float b3 = b[3 * DIM + d];

    float c1 = b0;
    float c2 = c1 + b1;
    float c3 = c2 + b2;
    g_Csum[d] = c3 + b3;

    float p1 = c1 * W[DIM + d];
    float p2 = c2 * W[2 * DIM + d];
    float p3 = c3 * W[3 * DIM + d];

    #pragma unroll
    for (int o = 16; o; o >>= 1) {
        p1 += __shfl_xor_sync(0xFFFFFFFFu, p1, o);
        p2 += __shfl_xor_sync(0xFFFFFFFFu, p2, o);
        p3 += __shfl_xor_sync(0xFFFFFFFFu, p3, o);
    }
    __shared__ float sm[3][32];
    int warp = threadIdx.x >> 5;
    int lane = threadIdx.x & 31;
    if (lane == 0) { sm[0][warp] = p1; sm[1][warp] = p2; sm[2][warp] = p3; }
    __syncthreads();
    if (warp == 0) {
        float q1 = sm[0][lane];
        float q2 = sm[1][lane];
        float q3 = sm[2][lane];
        #pragma unroll
        for (int o = 16; o; o >>= 1) {
            q1 += __shfl_xor_sync(0xFFFFFFFFu, q1, o);
            q2 += __shfl_xor_sync(0xFFFFFFFFu, q2, o);
            q3 += __shfl_xor_sync(0xFFFFFFFFu, q3, o);
        }
        if (lane == 0) {
            g_D[0] = 0.0f; g_D[1] = q1; g_D[2] = q2; g_D[3] = q3;
        }
    }
}

// ---------------------------------------------------------------------------
// Main kernel: ONE row per warp, 4 CTAs/SM (32 warps).
//  - W + Csum in shared (LDG queue = pure x0 traffic).
//  - 8 x-loads front-batched (32 regs) -> total ~56-60 regs -> 4 CTAs/SM.
//  - Same 256 outstanding LDG.128/SM as R4, but 2x warps to hide tails.
// ---------------------------------------------------------------------------
#define TPB 256
#define WARPS_PER_CTA 8
#define ROWS_PER_CTA WARPS_PER_CTA          // 8 (1 row per warp)
#define GRID (BATCH / ROWS_PER_CTA)         // 2048

__device__ __forceinline__ float dot4(float4 x, float4 w, float acc) {
    return fmaf(x.x, w.x, fmaf(x.y, w.y, fmaf(x.z, w.z, fmaf(x.w, w.w, acc))));
}

__global__ __launch_bounds__(TPB, 4) void crossnet_main(
    const float4* __restrict__ x0,
    const float4* __restrict__ W4,
    float4* __restrict__ out)
{
    __shared__ float4 sW[NL][DIM4];   // 16 KB
    __shared__ float4 sC[DIM4];       //  4 KB
    __shared__ float  sD[NL];

    const int tid  = threadIdx.x;
    const int warp = tid >> 5;
    const int lane = tid & 31;

    // one-time smem fill (DIM4 == TPB)
    sW[0][tid] = W4[tid];
    sW[1][tid] = W4[DIM4 + tid];
    sW[2][tid] = W4[2 * DIM4 + tid];
    sW[3][tid] = W4[3 * DIM4 + tid];
    sC[tid]    = ((const float4*)g_Csum)[tid];
    if (tid < NL) sD[tid] = g_D[tid];
    __syncthreads();

    const int row = blockIdx.x * WARPS_PER_CTA + warp;
    const float4* __restrict__ xr = x0 + (size_t)row * DIM4;

    // ---- front-batch all 8 x loads (DRAM-miss stream) ----
    float4 xv[8];
    #pragma unroll
    for (int k = 0; k < 8; k++)
        xv[k] = xr[k * 32 + lane];

    // ---- 4 dot products vs smem W ----
    float u0 = 0.f, u1 = 0.f, u2 = 0.f, u3 = 0.f;
    #pragma unroll
    for (int k = 0; k < 8; k++) {
        const int i = k * 32 + lane;
        u0 = dot4(xv[k], sW[0][i], u0);
        u1 = dot4(xv[k], sW[1][i], u1);
        u2 = dot4(xv[k], sW[2][i], u2);
        u3 = dot4(xv[k], sW[3][i], u3);
    }

    #pragma unroll
    for (int o = 16; o; o >>= 1) {
        u0 += __shfl_xor_sync(0xFFFFFFFFu, u0, o);
        u1 += __shfl_xor_sync(0xFFFFFFFFu, u1, o);
        u2 += __shfl_xor_sync(0xFFFFFFFFu, u2, o);
        u3 += __shfl_xor_sync(0xFFFFFFFFu, u3, o);
    }

    // ---- scalar recurrence: a_{l+1} = a_l + (a_l*u_l + D_l), D0 == 0 ----
    float a = 1.0f + u0;
    a += fmaf(a, u1, sD[1]);
    a += fmaf(a, u2, sD[2]);
    a += fmaf(a, u3, sD[3]);

    // ---- write: out = a * x0 + Csum, streaming stores ----
    float4* __restrict__ orow = out + (size_t)row * DIM4;
    #pragma unroll
    for (int k = 0; k < 8; k++) {
        const int i = k * 32 + lane;
        float4 c = sC[i];
        float4 r;
        r.x = fmaf(a, xv[k].x, c.x);
        r.y = fmaf(a, xv[k].y, c.y);
        r.z = fmaf(a, xv[k].z, c.z);
        r.w = fmaf(a, xv[k].w, c.w);
        __stcs(&orow[i], r);
    }
}

extern "C" void kernel_launch(void* const* d_in, const int* in_sizes, int n_in,
                              void* d_out, int out_size)
{
    const float* x0 = (const float*)d_in[0];   // [16384, 1024]
    const float* W  = (const float*)d_in[1];   // [4, 1024]
    const float* b  = (const float*)d_in[2];   // [4, 1024]
    float* out      = (float*)d_out;           // [16384, 1024]

    crossnet_precompute<<<1, DIM>>>(W, b);
    crossnet_main<<<GRID, TPB>>>((const float4*)x0, (const float4*)W,
                                 (float4*)out);
}

// round 10
// speedup vs baseline: 1.1664x; 1.1664x over previous
#include <cuda_runtime.h>
#include <cuda_bf16.h>

#define BATCH 16384
#define DIM   1024
#define DIM4  (DIM / 4)       // 256 float4 per row
#define NL    4

__device__ float g_D[NL];     // D_l = dot(c_l, W_l), c_l = sum_{j<l} b_j
__device__ float g_Csum[DIM]; // b0+b1+b2+b3

// ---------------------------------------------------------------------------
// Precompute: 1 CTA, 1024 threads, reads 32 KB.
// ---------------------------------------------------------------------------
__global__ __launch_bounds__(DIM) void crossnet_precompute(
    const float* __restrict__ W, const float* __restrict__ b)
{
    int d = threadIdx.x;
    float b0 = b[d];
    float b1 = b[DIM + d];
    float b2 = b[2 * DIM + d];
    float b3 = b[3 * DIM + d];

    float c1 = b0;
    float c2 = c1 + b1;
    float c3 = c2 + b2;
    g_Csum[d] = c3 + b3;

    float p1 = c1 * W[DIM + d];
    float p2 = c2 * W[2 * DIM + d];
    float p3 = c3 * W[3 * DIM + d];

    #pragma unroll
    for (int o = 16; o; o >>= 1) {
        p1 += __shfl_xor_sync(0xFFFFFFFFu, p1, o);
        p2 += __shfl_xor_sync(0xFFFFFFFFu, p2, o);
        p3 += __shfl_xor_sync(0xFFFFFFFFu, p3, o);
    }
    __shared__ float sm[3][32];
    int warp = threadIdx.x >> 5;
    int lane = threadIdx.x & 31;
    if (lane == 0) { sm[0][warp] = p1; sm[1][warp] = p2; sm[2][warp] = p3; }
    __syncthreads();
    if (warp == 0) {
        float q1 = sm[0][lane];
        float q2 = sm[1][lane];
        float q3 = sm[2][lane];
        #pragma unroll
        for (int o = 16; o; o >>= 1) {
            q1 += __shfl_xor_sync(0xFFFFFFFFu, q1, o);
            q2 += __shfl_xor_sync(0xFFFFFFFFu, q2, o);
            q3 += __shfl_xor_sync(0xFFFFFFFFu, q3, o);
        }
        if (lane == 0) {
            g_D[0] = 0.0f; g_D[1] = q1; g_D[2] = q2; g_D[3] = q3;
        }
    }
}

// ---------------------------------------------------------------------------
// Main kernel: THREE rows per warp, 24-deep front-batched LDG stream.
//  - W + Csum in shared; W-LDS amortized over 3 rows (10.7/row).
//  - launch_bounds(256,2): <=128 regs, 2 CTAs/SM, 16 warps/SM.
//  - Partial last CTA handled by clamping rows to BATCH-1 (benign dup write).
// ---------------------------------------------------------------------------
#define TPB 256
#define WARPS_PER_CTA 8
#define ROWS_PER_WARP 3
#define ROWS_PER_CTA (WARPS_PER_CTA * ROWS_PER_WARP)   // 24
#define GRID ((BATCH + ROWS_PER_CTA - 1) / ROWS_PER_CTA)  // 683

__device__ __forceinline__ float dot4(float4 x, float4 w, float acc) {
    return fmaf(x.x, w.x, fmaf(x.y, w.y, fmaf(x.z, w.z, fmaf(x.w, w.w, acc))));
}

__global__ __launch_bounds__(TPB, 2) void crossnet_main(
    const float4* __restrict__ x0,
    const float4* __restrict__ W4,
    float4* __restrict__ out)
{
    __shared__ float4 sW[NL][DIM4];   // 16 KB
    __shared__ float4 sC[DIM4];       //  4 KB
    __shared__ float  sD[NL];

    const int tid  = threadIdx.x;
    const int warp = tid >> 5;
    const int lane = tid & 31;

    // one-time smem fill (DIM4 == TPB)
    sW[0][tid] = W4[tid];
    sW[1][tid] = W4[DIM4 + tid];
    sW[2][tid] = W4[2 * DIM4 + tid];
    sW[3][tid] = W4[3 * DIM4 + tid];
    sC[tid]    = ((const float4*)g_Csum)[tid];
    if (tid < NL) sD[tid] = g_D[tid];
    __syncthreads();

    const int base = blockIdx.x * ROWS_PER_CTA + warp * ROWS_PER_WARP;
    const int rA = min(base,     BATCH - 1);
    const int rB = min(base + 1, BATCH - 1);
    const int rC = min(base + 2, BATCH - 1);

    const float4* __restrict__ xa = x0 + (size_t)rA * DIM4;
    const float4* __restrict__ xb = x0 + (size_t)rB * DIM4;
    const float4* __restrict__ xc = x0 + (size_t)rC * DIM4;

    // ---- front-batch all 24 x loads (DRAM-miss stream) ----
    float4 xA[8], xB[8], xC[8];
    #pragma unroll
    for (int k = 0; k < 8; k++) {
        const int i = k * 32 + lane;
        xA[k] = xa[i];
        xB[k] = xb[i];
        xC[k] = xc[i];
    }

    // ---- 12 dot products vs smem W ----
    float uA0 = 0.f, uA1 = 0.f, uA2 = 0.f, uA3 = 0.f;
    float uB0 = 0.f, uB1 = 0.f, uB2 = 0.f, uB3 = 0.f;
    float uC0 = 0.f, uC1 = 0.f, uC2 = 0.f, uC3 = 0.f;
    #pragma unroll
    for (int k = 0; k < 8; k++) {
        const int i = k * 32 + lane;
        float4 w0 = sW[0][i];
        float4 w1 = sW[1][i];
        float4 w2 = sW[2][i];
        float4 w3 = sW[3][i];
        uA0 = dot4(xA[k], w0, uA0); uB0 = dot4(xB[k], w0, uB0); uC0 = dot4(xC[k], w0, uC0);
        uA1 = dot4(xA[k], w1, uA1); uB1 = dot4(xB[k], w1, uB1); uC1 = dot4(xC[k], w1, uC1);
        uA2 = dot4(xA[k], w2, uA2); uB2 = dot4(xB[k], w2, uB2); uC2 = dot4(xC[k], w2, uC2);
        uA3 = dot4(xA[k], w3, uA3); uB3 = dot4(xB[k], w3, uB3); uC3 = dot4(xC[k], w3, uC3);
    }

    #pragma unroll
    for (int o = 16; o; o >>= 1) {
        uA0 += __shfl_xor_sync(0xFFFFFFFFu, uA0, o);
        uA1 += __shfl_xor_sync(0xFFFFFFFFu, uA1, o);
        uA2 += __shfl_xor_sync(0xFFFFFFFFu, uA2, o);
        uA3 += __shfl_xor_sync(0xFFFFFFFFu, uA3, o);
        uB0 += __shfl_xor_sync(0xFFFFFFFFu, uB0, o);
        uB1 += __shfl_xor_sync(0xFFFFFFFFu, uB1, o);
        uB2 += __shfl_xor_sync(0xFFFFFFFFu, uB2, o);
        uB3 += __shfl_xor_sync(0xFFFFFFFFu, uB3, o);
        uC0 += __shfl_xor_sync(0xFFFFFFFFu, uC0, o);
        uC1 += __shfl_xor_sync(0xFFFFFFFFu, uC1, o);
        uC2 += __shfl_xor_sync(0xFFFFFFFFu, uC2, o);
        uC3 += __shfl_xor_sync(0xFFFFFFFFu, uC3, o);
    }

    const float D1 = sD[1], D2 = sD[2], D3 = sD[3];

    float aA = 1.0f + uA0;                 // D0 == 0
    aA += fmaf(aA, uA1, D1);
    aA += fmaf(aA, uA2, D2);
    aA += fmaf(aA, uA3, D3);

    float aB = 1.0f + uB0;
    aB += fmaf(aB, uB1, D1);
    aB += fmaf(aB, uB2, D2);
    aB += fmaf(aB, uB3, D3);

    float aC = 1.0f + uC0;
    aC += fmaf(aC, uC1, D1);
    aC += fmaf(aC, uC2, D2);
    aC += fmaf(aC, uC3, D3);

    // ---- write: out = a * x0 + Csum (clamped dup rows write identical data)
    float4* __restrict__ oa = out + (size_t)rA * DIM4;
    float4* __restrict__ ob = out + (size_t)rB * DIM4;
    float4* __restrict__ oc = out + (size_t)rC * DIM4;

    #pragma unroll
    for (int k = 0; k < 8; k++) {
        const int i = k * 32 + lane;
        float4 c = sC[i];
        float4 rA4, rB4, rC4;
        rA4.x = fmaf(aA, xA[k].x, c.x); rA4.y = fmaf(aA, xA[k].y, c.y);
        rA4.z = fmaf(aA, xA[k].z, c.z); rA4.w = fmaf(aA, xA[k].w, c.w);
        rB4.x = fmaf(aB, xB[k].x, c.x); rB4.y = fmaf(aB, xB[k].y, c.y);
        rB4.z = fmaf(aB, xB[k].z, c.z); rB4.w = fmaf(aB, xB[k].w, c.w);
        rC4.x = fmaf(aC, xC[k].x, c.x); rC4.y = fmaf(aC, xC[k].y, c.y);
        rC4.z = fmaf(aC, xC[k].z, c.z); rC4.w = fmaf(aC, xC[k].w, c.w);
        __stcs(&oa[i], rA4);
        __stcs(&ob[i], rB4);
        __stcs(&oc[i], rC4);
    }
}

extern "C" void kernel_launch(void* const* d_in, const int* in_sizes, int n_in,
                              void* d_out, int out_size)
{
    const float* x0 = (const float*)d_in[0];   // [16384, 1024]
    const float* W  = (const float*)d_in[1];   // [4, 1024]
    const float* b  = (const float*)d_in[2];   // [4, 1024]
    float* out      = (float*)d_out;           // [16384, 1024]

    crossnet_precompute<<<1, DIM>>>(W, b);
    crossnet_main<<<GRID, TPB>>>((const float4*)x0, (const float4*)W,
                                 (float4*)out);
}